// round 12
// baseline (speedup 1.0000x reference)
#include <cuda_runtime.h>
#include <math.h>

#define T 20
#define NC 80
#define BS 32
#define FULL 0xffffffffu

__constant__ float c_anch[3][3][2] = {
    {{116.f, 90.f}, {156.f, 198.f}, {373.f, 326.f}},
    {{ 30.f, 61.f}, { 62.f,  45.f}, { 59.f, 119.f}},
    {{ 10.f, 13.f}, { 16.f,  30.f}, { 33.f,  23.f}}
};

__device__ __forceinline__ float tanh_ap(float x) {
    float r; asm("tanh.approx.f32 %0, %1;" : "=f"(r) : "f"(x)); return r;
}
// stable softplus, fast intrinsics
__device__ __forceinline__ float sp(float z) {
    return fmaxf(z, 0.f) + __logf(1.f + __expf(-fabsf(z)));
}

template<int LVL, int W, int HW>
__device__ __forceinline__ void level_body(
    float* wred, int nblk, int b,
    const float* __restrict__ x,
    const float* __restrict__ gtb,
    const int*   __restrict__ gtl,
    float* __restrict__ out)
{
    constexpr int   N      = 3 * HW;
    constexpr float stride = (LVL == 0) ? 32.f : (LVL == 1) ? 16.f : 8.f;
    constexpr float inv_s  = 1.f / stride;   // exact power-of-two scale
    const int tid  = threadIdx.x;
    const int lane = tid & 31;
    const int wrp  = tid >> 5;

    float sax[3], say[3];
#pragma unroll
    for (int a = 0; a < 3; a++) {
        sax[a] = c_anch[LVL][a][0] * inv_s;
        say[a] = c_anch[LVL][a][1] * inv_s;
    }

    const int base = nblk * 256;

    // ---- lane-parallel target records; persistent: tb (4 regs) + rec (1 reg) ----
    float4 tb = make_float4(-1e30f, -1e30f, -1e30f, -1e30f);  // sentinel fails screen
    int    rec = 0x7fffffff;    // flat[0:13) | label[13:20) | win[20]; flat=0x1fff never matches
    {
        unsigned key = 0x80000000u | lane;
        if (lane < T) {
            float4 gv = __ldg((const float4*)gtb + b * T + lane);
            bool valid = (gv.x != -1.f) || (gv.y != -1.f) || (gv.z != -1.f) || (gv.w != -1.f);
            if (valid) {
                tb.x = gv.x * inv_s; tb.y = gv.y * inv_s;
                tb.z = gv.z * inv_s; tb.w = gv.w * inv_s;
                float gw = tb.z - tb.x, gh = tb.w - tb.y;
                float gxc = (tb.x + tb.z) * 0.5f;
                float gyc = (tb.y + tb.w) * 0.5f;
                int gi = min(max((int)gxc, 0), W - 1);
                int gj = min(max((int)gyc, 0), W - 1);
                int best = 0; float bi = -1.f;
#pragma unroll
                for (int a = 0; a < 3; a++) {
                    float inter = fminf(gw, sax[a]) * fminf(gh, say[a]);
                    float u = gw * gh + sax[a] * say[a] - inter + 1e-16f;
                    float io = inter / u;
                    if (io > bi) { bi = io; best = a; }
                }
                int flat = best * HW + gj * W + gi;
                key = (unsigned)flat;
                int lab = min(max(__ldg(gtl + b * T + lane), 0), NC - 1);
                rec = flat | (lab << 13);
            }
        }
        // last-writer-wins: winner of each flat-group = highest lane in match group
        unsigned mm = __match_any_sync(FULL, key);
        if (!(key >> 31) && ((31 - __clz(mm)) == lane)) rec |= (1 << 20);
    }

    const size_t base_b = (size_t)b * 255 * HW;
    float loss = 0.f;
    float tprod = 1.f, bacc = 0.f;    // batched negative-conf softplus accumulators

    // ================= per-cell processing (sequential -> short live ranges) ======
#pragma unroll
    for (int c = 0; c < 2; c++) {
        const int n   = base + 128 * c + tid;
        const bool act = (n < N);
        const int ncl = act ? n : (N - 1);

        int aa  = ncl / HW;                 // compile-time magic div
        int rem = ncl - aa * HW;
        int jj  = rem / W;
        int ii  = rem - jj * W;
        const int off = aa * (85 * HW) + rem;
        const float* xp = x + base_b + off;

        // ---- issue loads FIRST (latency overlaps the screen) ----
        float zx = 0.f, zy = 0.f, zw = 0.f, zh = 0.f, zc = 0.f;
        if (act) {
            zx = xp[0]; zy = xp[HW]; zw = xp[2*HW]; zh = xp[3*HW]; zc = xp[4*HW];
        }

        // ---- screen: warp window vs target boxes ----
        int imin = __reduce_min_sync(FULL, ii), imax = __reduce_max_sync(FULL, ii);
        int jmin = __reduce_min_sync(FULL, jj), jmax = __reduce_max_sync(FULL, jj);
        bool ov = (tb.x <= (float)(imax + 1)) && (tb.z >= (float)imin)
               && (tb.y <= (float)(jmax + 1)) && (tb.w >= (float)jmin);
        const unsigned mask = __ballot_sync(FULL, ov);

        bool neg;
        if (mask) {   // warp-uniform slow path
            float sx = 0.5f * tanh_ap(0.5f * zx) + 0.5f;
            float sy = 0.5f * tanh_ap(0.5f * zy) + 0.5f;
            float cx = sx + (float)ii, cy = sy + (float)jj;
            float sxa = (aa == 0) ? sax[0] : (aa == 1) ? sax[1] : sax[2];
            float sya = (aa == 0) ? say[0] : (aa == 1) ? say[1] : say[2];
            float bw = __expf(zw) * sxa, bh = __expf(zh) * sya;
            float px1 = cx - 0.5f*bw, py1 = cy - 0.5f*bh;
            float px2 = cx + 0.5f*bw, py2 = cy + 0.5f*bh;
            float ap  = act ? (bw * bh) : 1e30f;

            int Lig = -1, Lp = -1;
            unsigned cm0 = 0, cm1 = 0, cm2 = 0;
            unsigned m = mask;
            do {
                int t = __ffs(m) - 1; m &= m - 1;
                float bx1t = __shfl_sync(FULL, tb.x, t);
                float by1t = __shfl_sync(FULL, tb.y, t);
                float bx2t = __shfl_sync(FULL, tb.z, t);
                float by2t = __shfl_sync(FULL, tb.w, t);
                int   rt   = __shfl_sync(FULL, rec,  t);
                float ae   = (bx2t - bx1t) * (by2t - by1t) + 1e-16f;
                float iw = fminf(px2, bx2t) - fmaxf(px1, bx1t);
                float ih = fminf(py2, by2t) - fmaxf(py1, by1t);
                float in_ = fmaxf(iw, 0.f) * fmaxf(ih, 0.f);
                if (fmaf(3.f, in_, -ap) > ae) Lig = t;      // ascending: last = max t
                if ((rt & 0x1fff) == n) {
                    int l = (rt >> 13) & 0x7f;
                    if (l < 32) cm0 |= 1u << l; else if (l < 64) cm1 |= 1u << (l-32); else cm2 |= 1u << (l-64);
                    if (rt & (1 << 20)) Lp = t;
                }
            } while (m);

            const bool pos = act && (Lp >= 0) && (Lp >= Lig);
            neg = act && (Lig < 0) && !pos;

            // pos losses: recompute winner target in a warp-uniform rare block
            if (__any_sync(FULL, pos)) {
                int s = max(Lp, 0);
                float wx1 = __shfl_sync(FULL, tb.x, s);
                float wy1 = __shfl_sync(FULL, tb.y, s);
                float wx2 = __shfl_sync(FULL, tb.z, s);
                float wy2 = __shfl_sync(FULL, tb.w, s);
                float gw = wx2 - wx1, gh = wy2 - wy1;
                float gxc = (wx1 + wx2) * 0.5f, gyc = (wy1 + wy2) * 0.5f;
                int gi = min(max((int)gxc, 0), W - 1);
                int gj = min(max((int)gyc, 0), W - 1);
                int best = 0; float bi = -1.f;
#pragma unroll
                for (int a = 0; a < 3; a++) {
                    float inter = fminf(gw, sax[a]) * fminf(gh, say[a]);
                    float u = gw * gh + sax[a] * say[a] - inter + 1e-16f;
                    float io = inter / u;
                    if (io > bi) { bi = io; best = a; }
                }
                float bsx = (best == 0) ? sax[0] : (best == 1) ? sax[1] : sax[2];
                float bsy = (best == 0) ? say[0] : (best == 1) ? say[1] : say[2];
                float tgx = gxc - (float)gi, tgy = gyc - (float)gj;
                float tgw = __logf(gw / bsx + 1e-16f);
                float tgh = __logf(gh / bsy + 1e-16f);
                if (pos) {
                    float bxl = tgx * sp(-zx) + (1.f - tgx) * sp(zx);
                    float byl = tgy * sp(-zy) + (1.f - tgy) * sp(zy);
                    float dw = zw - tgw, dh = zh - tgh;
                    loss += 2.5f * (bxl + byl + dw*dw + dh*dh) + sp(-zc);
                }
            }

            // warp-cooperative class loss (rare positives)
            // BCE(sig(z),1) = sp(z) - z ; BCE(sig(z),0) = sp(z)
            unsigned bal = __ballot_sync(FULL, pos);
            while (bal) {
                int src = __ffs(bal) - 1;
                bal &= bal - 1;
                int offs    = __shfl_sync(FULL, off, src);
                unsigned M0 = __shfl_sync(FULL, cm0, src);
                unsigned M1 = __shfl_sync(FULL, cm1, src);
                unsigned M2 = __shfl_sync(FULL, cm2, src);
                const float* cps = x + base_b + offs + (size_t)5 * HW;
                float z = __ldg(cps + (size_t)lane * HW);
                float acc = sp(z) - (((M0 >> lane) & 1u) ? z : 0.f);
                z = __ldg(cps + (size_t)(lane + 32) * HW);
                acc += sp(z) - (((M1 >> lane) & 1u) ? z : 0.f);
                if (lane < 16) {
                    z = __ldg(cps + (size_t)(lane + 64) * HW);
                    acc += sp(z) - (((M2 >> lane) & 1u) ? z : 0.f);
                }
                loss += acc;
            }
        } else {      // warp-uniform fast path: nothing can ignore or own these cells
            neg = act;
        }

        // batched negative conf: sp(z) = max(z,0) + log1p(e^-|z|)
        float e = __expf(-fabsf(zc));
        tprod *= neg ? (1.f + e) : 1.f;
        bacc  += neg ? fmaxf(zc, 0.f) : 0.f;
    }

    loss += bacc + __logf(tprod);

    // ---- reduction (only barrier in the kernel) ----
#pragma unroll
    for (int o = 16; o > 0; o >>= 1)
        loss += __shfl_down_sync(FULL, loss, o);
    if (lane == 0) wred[wrp] = loss;
    __syncthreads();
    if (wrp == 0) {
        float v = (lane < 4) ? wred[lane] : 0.f;
#pragma unroll
        for (int o = 2; o > 0; o >>= 1)
            v += __shfl_down_sync(FULL, v, o);
        if (lane == 0) atomicAdd(out, v * (1.f / (float)BS));
    }
}

// grid: (42, 32). bx<2 -> lvl0; [2,10) -> lvl1; [10,42) -> lvl2.
// 128 threads x 2 strided cells = 256 cells/block; fine granularity for balance,
// 12 blocks/SM capacity -> single wave at 1344 blocks.
__global__ __launch_bounds__(128, 12)
void yolo_loss_kernel(const float* __restrict__ x0,
                      const float* __restrict__ x1,
                      const float* __restrict__ x2,
                      const float* __restrict__ gtb,
                      const int*   __restrict__ gtl,
                      float* __restrict__ out)
{
    __shared__ float wred[4];
    const int bx = blockIdx.x;
    const int b  = blockIdx.y;
    if (bx < 2)       level_body<0, 13, 169 >(wred, bx,      b, x0, gtb, gtl, out);
    else if (bx < 10) level_body<1, 26, 676 >(wred, bx - 2,  b, x1, gtb, gtl, out);
    else              level_body<2, 52, 2704>(wred, bx - 10, b, x2, gtb, gtl, out);
}

extern "C" void kernel_launch(void* const* d_in, const int* in_sizes, int n_in,
                              void* d_out, int out_size)
{
    const float* x0  = (const float*)d_in[0];
    const float* x1  = (const float*)d_in[1];
    const float* x2  = (const float*)d_in[2];
    const float* gtb = (const float*)d_in[3];
    const int*   gtl = (const int*)  d_in[4];
    float* out = (float*)d_out;

    cudaMemsetAsync(out, 0, sizeof(float));
    dim3 grid(42, BS);
    yolo_loss_kernel<<<grid, 128>>>(x0, x1, x2, gtb, gtl, out);
}

// round 13
// speedup vs baseline: 1.1180x; 1.1180x over previous
#include <cuda_runtime.h>
#include <math.h>

#define T 20
#define NC 80
#define BS 32
#define FULL 0xffffffffu

__constant__ float c_anch[3][3][2] = {
    {{116.f, 90.f}, {156.f, 198.f}, {373.f, 326.f}},
    {{ 30.f, 61.f}, { 62.f,  45.f}, { 59.f, 119.f}},
    {{ 10.f, 13.f}, { 16.f,  30.f}, { 33.f,  23.f}}
};

__device__ __forceinline__ float tanh_ap(float x) {
    float r; asm("tanh.approx.f32 %0, %1;" : "=f"(r) : "f"(x)); return r;
}
// stable softplus, fast intrinsics
__device__ __forceinline__ float sp(float z) {
    return fmaxf(z, 0.f) + __logf(1.f + __expf(-fabsf(z)));
}

template<int LVL, int W, int HW>
__device__ __forceinline__ void level_body(
    float* wred, int nblk, int b,
    const float* __restrict__ x,
    const float* __restrict__ gtb,
    const int*   __restrict__ gtl,
    float* __restrict__ out)
{
    constexpr int   N      = 3 * HW;
    constexpr float stride = (LVL == 0) ? 32.f : (LVL == 1) ? 16.f : 8.f;
    constexpr float inv_s  = 1.f / stride;   // exact power-of-two scale
    const int tid  = threadIdx.x;
    const int lane = tid & 31;
    const int wrp  = tid >> 5;

    float sax[3], say[3];
#pragma unroll
    for (int a = 0; a < 3; a++) {
        sax[a] = c_anch[LVL][a][0] * inv_s;
        say[a] = c_anch[LVL][a][1] * inv_s;
    }

    const int base = nblk * 512;
    const size_t base_b = (size_t)b * 255 * HW;

    // ---- addressing for BOTH cells, then issue ALL 10 loads (MLP=10) ----
    int   nn[2], aa[2], iis[2], jjs[2], off[2];
    bool  acts[2];
    float z[2][5];
#pragma unroll
    for (int c = 0; c < 2; c++) {
        const int n = base + 256 * c + tid;
        acts[c] = (n < N);
        nn[c] = n;
        const int ncl = acts[c] ? n : (N - 1);
        int a_  = ncl / HW;                 // compile-time magic div
        int rem = ncl - a_ * HW;
        int j_  = rem / W;
        iis[c] = rem - j_ * W; jjs[c] = j_; aa[c] = a_;
        off[c] = a_ * (85 * HW) + rem;
        z[c][0] = z[c][1] = z[c][2] = z[c][3] = z[c][4] = 0.f;
        if (acts[c]) {
            const float* xp = x + base_b + off[c];
            z[c][0] = xp[0]; z[c][1] = xp[HW]; z[c][2] = xp[2*HW];
            z[c][3] = xp[3*HW]; z[c][4] = xp[4*HW];
        }
    }

    // ---- lane-parallel target records; persistent: tb (4 regs) + rec (1 reg) ----
    // (overlaps the in-flight channel loads)
    float4 tb = make_float4(-1e30f, -1e30f, -1e30f, -1e30f);  // sentinel fails screen
    int    rec = 0x7fffffff;    // flat[0:13) | label[13:20) | win[20]; flat=0x1fff never matches
    {
        unsigned key = 0x80000000u | lane;
        if (lane < T) {
            float4 gv = __ldg((const float4*)gtb + b * T + lane);
            bool valid = (gv.x != -1.f) || (gv.y != -1.f) || (gv.z != -1.f) || (gv.w != -1.f);
            if (valid) {
                tb.x = gv.x * inv_s; tb.y = gv.y * inv_s;
                tb.z = gv.z * inv_s; tb.w = gv.w * inv_s;
                float gw = tb.z - tb.x, gh = tb.w - tb.y;
                float gxc = (tb.x + tb.z) * 0.5f;
                float gyc = (tb.y + tb.w) * 0.5f;
                int gi = min(max((int)gxc, 0), W - 1);
                int gj = min(max((int)gyc, 0), W - 1);
                int best = 0; float bi = -1.f;
#pragma unroll
                for (int a = 0; a < 3; a++) {
                    float inter = fminf(gw, sax[a]) * fminf(gh, say[a]);
                    float u = gw * gh + sax[a] * say[a] - inter + 1e-16f;
                    float io = inter / u;
                    if (io > bi) { bi = io; best = a; }
                }
                int flat = best * HW + gj * W + gi;
                key = (unsigned)flat;
                int lab = min(max(__ldg(gtl + b * T + lane), 0), NC - 1);
                rec = flat | (lab << 13);
            }
        }
        // last-writer-wins: winner of each flat-group = highest lane in match group
        unsigned mm = __match_any_sync(FULL, key);
        if (!(key >> 31) && ((31 - __clz(mm)) == lane)) rec |= (1 << 20);
    }

    float loss = 0.f;
    float tprod = 1.f, bacc = 0.f;    // batched negative-conf softplus accumulators

    // ================= per-cell processing (sequential -> short live ranges) ======
#pragma unroll
    for (int c = 0; c < 2; c++) {
        const int  n   = nn[c];
        const bool act = acts[c];
        const int  ii = iis[c], jj = jjs[c];
        const float zx = z[c][0], zy = z[c][1], zw = z[c][2], zh = z[c][3], zc = z[c][4];

        // ---- screen: warp window vs target boxes ----
        int imin = __reduce_min_sync(FULL, ii), imax = __reduce_max_sync(FULL, ii);
        int jmin = __reduce_min_sync(FULL, jj), jmax = __reduce_max_sync(FULL, jj);
        bool ov = (tb.x <= (float)(imax + 1)) && (tb.z >= (float)imin)
               && (tb.y <= (float)(jmax + 1)) && (tb.w >= (float)jmin);
        const unsigned mask = __ballot_sync(FULL, ov);

        bool neg;
        if (mask) {   // warp-uniform slow path
            float sx = 0.5f * tanh_ap(0.5f * zx) + 0.5f;
            float sy = 0.5f * tanh_ap(0.5f * zy) + 0.5f;
            float cx = sx + (float)ii, cy = sy + (float)jj;
            int a_ = aa[c];
            float sxa = (a_ == 0) ? sax[0] : (a_ == 1) ? sax[1] : sax[2];
            float sya = (a_ == 0) ? say[0] : (a_ == 1) ? say[1] : say[2];
            float bw = __expf(zw) * sxa, bh = __expf(zh) * sya;
            float px1 = cx - 0.5f*bw, py1 = cy - 0.5f*bh;
            float px2 = cx + 0.5f*bw, py2 = cy + 0.5f*bh;
            float ap  = act ? (bw * bh) : 1e30f;

            int Lig = -1, Lp = -1;
            unsigned cm0 = 0, cm1 = 0, cm2 = 0;
            unsigned m = mask;
            do {
                int t = __ffs(m) - 1; m &= m - 1;
                float bx1t = __shfl_sync(FULL, tb.x, t);
                float by1t = __shfl_sync(FULL, tb.y, t);
                float bx2t = __shfl_sync(FULL, tb.z, t);
                float by2t = __shfl_sync(FULL, tb.w, t);
                int   rt   = __shfl_sync(FULL, rec,  t);
                float ae   = (bx2t - bx1t) * (by2t - by1t) + 1e-16f;
                float iw = fminf(px2, bx2t) - fmaxf(px1, bx1t);
                float ih = fminf(py2, by2t) - fmaxf(py1, by1t);
                float in_ = fmaxf(iw, 0.f) * fmaxf(ih, 0.f);
                if (fmaf(3.f, in_, -ap) > ae) Lig = t;      // ascending: last = max t
                if ((rt & 0x1fff) == n) {
                    int l = (rt >> 13) & 0x7f;
                    if (l < 32) cm0 |= 1u << l; else if (l < 64) cm1 |= 1u << (l-32); else cm2 |= 1u << (l-64);
                    if (rt & (1 << 20)) Lp = t;
                }
            } while (m);

            const bool pos = act && (Lp >= 0) && (Lp >= Lig);
            neg = act && (Lig < 0) && !pos;

            // pos losses: recompute winner target in a warp-uniform rare block
            if (__any_sync(FULL, pos)) {
                int s = max(Lp, 0);
                float wx1 = __shfl_sync(FULL, tb.x, s);
                float wy1 = __shfl_sync(FULL, tb.y, s);
                float wx2 = __shfl_sync(FULL, tb.z, s);
                float wy2 = __shfl_sync(FULL, tb.w, s);
                float gw = wx2 - wx1, gh = wy2 - wy1;
                float gxc = (wx1 + wx2) * 0.5f, gyc = (wy1 + wy2) * 0.5f;
                int gi = min(max((int)gxc, 0), W - 1);
                int gj = min(max((int)gyc, 0), W - 1);
                int best = 0; float bi = -1.f;
#pragma unroll
                for (int a = 0; a < 3; a++) {
                    float inter = fminf(gw, sax[a]) * fminf(gh, say[a]);
                    float u = gw * gh + sax[a] * say[a] - inter + 1e-16f;
                    float io = inter / u;
                    if (io > bi) { bi = io; best = a; }
                }
                float bsx = (best == 0) ? sax[0] : (best == 1) ? sax[1] : sax[2];
                float bsy = (best == 0) ? say[0] : (best == 1) ? say[1] : say[2];
                float tgx = gxc - (float)gi, tgy = gyc - (float)gj;
                float tgw = __logf(gw / bsx + 1e-16f);
                float tgh = __logf(gh / bsy + 1e-16f);
                if (pos) {
                    // t*sp(-z) + (1-t)*sp(z) = sp(z) - t*z
                    float bxl = sp(zx) - tgx * zx;
                    float byl = sp(zy) - tgy * zy;
                    float dw = zw - tgw, dh = zh - tgh;
                    loss += 2.5f * (bxl + byl + dw*dw + dh*dh) + sp(-zc);
                }
            }

            // warp-cooperative class loss (rare positives)
            // BCE(sig(z),1) = sp(z) - z ; BCE(sig(z),0) = sp(z)
            unsigned bal = __ballot_sync(FULL, pos);
            while (bal) {
                int src = __ffs(bal) - 1;
                bal &= bal - 1;
                int offs    = __shfl_sync(FULL, off[c], src);
                unsigned M0 = __shfl_sync(FULL, cm0, src);
                unsigned M1 = __shfl_sync(FULL, cm1, src);
                unsigned M2 = __shfl_sync(FULL, cm2, src);
                const float* cps = x + base_b + offs + (size_t)5 * HW;
                float zv = __ldg(cps + (size_t)lane * HW);
                float acc = sp(zv) - (((M0 >> lane) & 1u) ? zv : 0.f);
                zv = __ldg(cps + (size_t)(lane + 32) * HW);
                acc += sp(zv) - (((M1 >> lane) & 1u) ? zv : 0.f);
                if (lane < 16) {
                    zv = __ldg(cps + (size_t)(lane + 64) * HW);
                    acc += sp(zv) - (((M2 >> lane) & 1u) ? zv : 0.f);
                }
                loss += acc;
            }
        } else {      // warp-uniform fast path: nothing can ignore or own these cells
            neg = act;
        }

        // batched negative conf: sp(z) = max(z,0) + log1p(e^-|z|)
        float e = __expf(-fabsf(zc));
        tprod *= neg ? (1.f + e) : 1.f;
        bacc  += neg ? fmaxf(zc, 0.f) : 0.f;
    }

    loss += bacc + __logf(tprod);

    // ---- reduction (only barrier in the kernel) ----
#pragma unroll
    for (int o = 16; o > 0; o >>= 1)
        loss += __shfl_down_sync(FULL, loss, o);
    if (lane == 0) wred[wrp] = loss;
    __syncthreads();
    if (wrp == 0) {
        float v = (lane < 8) ? wred[lane] : 0.f;
#pragma unroll
        for (int o = 4; o > 0; o >>= 1)
            v += __shfl_down_sync(FULL, v, o);
        if (lane == 0) atomicAdd(out, v * (1.f / (float)BS));
    }
}

// grid: (21, 32). bx==0 -> lvl0; [1,5) -> lvl1; [5,21) -> lvl2.
// 256 threads x 2 strided cells; loads for both cells hoisted (MLP=10);
// 5 blocks/SM -> 40 warps/SM, single wave.
__global__ __launch_bounds__(256, 5)
void yolo_loss_kernel(const float* __restrict__ x0,
                      const float* __restrict__ x1,
                      const float* __restrict__ x2,
                      const float* __restrict__ gtb,
                      const int*   __restrict__ gtl,
                      float* __restrict__ out)
{
    __shared__ float wred[8];
    const int bx = blockIdx.x;
    const int b  = blockIdx.y;
    if (bx == 0)      level_body<0, 13, 169 >(wred, 0,      b, x0, gtb, gtl, out);
    else if (bx < 5)  level_body<1, 26, 676 >(wred, bx - 1, b, x1, gtb, gtl, out);
    else              level_body<2, 52, 2704>(wred, bx - 5, b, x2, gtb, gtl, out);
}

extern "C" void kernel_launch(void* const* d_in, const int* in_sizes, int n_in,
                              void* d_out, int out_size)
{
    const float* x0  = (const float*)d_in[0];
    const float* x1  = (const float*)d_in[1];
    const float* x2  = (const float*)d_in[2];
    const float* gtb = (const float*)d_in[3];
    const int*   gtl = (const int*)  d_in[4];
    float* out = (float*)d_out;

    cudaMemsetAsync(out, 0, sizeof(float));
    dim3 grid(21, BS);
    yolo_loss_kernel<<<grid, 256>>>(x0, x1, x2, gtb, gtl, out);
}